// round 1
// baseline (speedup 1.0000x reference)
#include <cuda_runtime.h>

#define NN 100000
#define EE 1200000
#define HH 64
#define BB 1000
#define CC 10
#define BN_EPS 1e-5f

// Scratch (device globals; no allocation allowed)
__device__ __align__(16) float g_agg1[NN * HH];     // x + scatter(x)
__device__ __align__(16) float g_h1b[NN * HH];      // output of MLP1
__device__ __align__(16) float g_agg2[NN * HH];     // h1b + scatter(h1b)
__device__ __align__(16) float g_xstruct[BB * HH];  // pooled per-graph features

__device__ __forceinline__ void red_add_v4(float* p, float4 v) {
    asm volatile("red.global.add.v4.f32 [%0], {%1,%2,%3,%4};"
                 :: "l"(p), "f"(v.x), "f"(v.y), "f"(v.z), "f"(v.w)
                 : "memory");
}

// ---------------------------------------------------------------------------
// K1: agg1 = x (self term); xstruct = 0
// ---------------------------------------------------------------------------
__global__ void init_kernel(const float* __restrict__ x) {
    int i = blockIdx.x * 256 + threadIdx.x;
    if (i < NN * HH) g_agg1[i] = x[i];
    if (i < BB * HH) g_xstruct[i] = 0.0f;
}

// ---------------------------------------------------------------------------
// K2: agg1[dst] += x[src]  (16 threads per edge, float4 chunks)
// ---------------------------------------------------------------------------
__global__ void edge_agg1_kernel(const float* __restrict__ x,
                                 const int* __restrict__ ei) {
    int tid = blockIdx.x * 256 + threadIdx.x;
    if (tid >= EE * 16) return;
    int eid = tid >> 4;
    int c   = (tid & 15) * 4;
    int s = ei[eid];
    int d = ei[EE + eid];
    float4 v = *(const float4*)(x + (size_t)s * HH + c);
    red_add_v4(g_agg1 + (size_t)d * HH + c, v);
}

// K4: agg2[dst] += h1b[src]
__global__ void edge_agg2_kernel(const int* __restrict__ ei) {
    int tid = blockIdx.x * 256 + threadIdx.x;
    if (tid >= EE * 16) return;
    int eid = tid >> 4;
    int c   = (tid & 15) * 4;
    int s = ei[eid];
    int d = ei[EE + eid];
    float4 v = *(const float4*)(g_h1b + (size_t)s * HH + c);
    red_add_v4(g_agg2 + (size_t)d * HH + c, v);
}

// ---------------------------------------------------------------------------
// K3: MLP1: h1b = relu( relu(BN(agg1 @ W1a + b1a)) @ W1b + b1b )
//     BN folded into Wa columns + bias. Also seeds agg2 = h1b (self term).
// blockDim (16,16): tx -> 4 output cols, ty -> node within tile of 16.
// ---------------------------------------------------------------------------
__global__ __launch_bounds__(256) void mlp1_kernel(
    const float* __restrict__ W1a, const float* __restrict__ b1a,
    const float* __restrict__ g1,  const float* __restrict__ be1,
    const float* __restrict__ m1,  const float* __restrict__ v1,
    const float* __restrict__ W1b, const float* __restrict__ b1b)
{
    __shared__ float Wa[64 * 64];
    __shared__ float Wb[64 * 64];
    __shared__ float bias1[64], bias2[64], scl[64];
    __shared__ float rowbuf[16][64];
    __shared__ float midbuf[16][64];

    const int tx = threadIdx.x;          // 0..15
    const int ty = threadIdx.y;          // 0..15
    const int tid = ty * 16 + tx;

    if (tid < 64) {
        float s = g1[tid] * rsqrtf(v1[tid] + BN_EPS);
        scl[tid]   = s;
        bias1[tid] = b1a[tid] * s + be1[tid] - m1[tid] * s;
        bias2[tid] = b1b[tid];
    }
    __syncthreads();
    for (int idx = tid; idx < 4096; idx += 256) {
        Wa[idx] = W1a[idx] * scl[idx & 63];
        Wb[idx] = W1b[idx];
    }
    __syncthreads();

    for (int n0 = blockIdx.x * 16; n0 < NN; n0 += gridDim.x * 16) {
        int node = n0 + ty;
        bool valid = node < NN;
        if (valid)
            *(float4*)&rowbuf[ty][tx * 4] =
                *(const float4*)(g_agg1 + (size_t)node * 64 + tx * 4);
        __syncwarp();

        float4 acc = *(float4*)&bias1[tx * 4];
        #pragma unroll 16
        for (int k = 0; k < 64; k++) {
            float  r = rowbuf[ty][k];
            float4 w = *(float4*)&Wa[k * 64 + tx * 4];
            acc.x += r * w.x; acc.y += r * w.y;
            acc.z += r * w.z; acc.w += r * w.w;
        }
        acc.x = fmaxf(acc.x, 0.f); acc.y = fmaxf(acc.y, 0.f);
        acc.z = fmaxf(acc.z, 0.f); acc.w = fmaxf(acc.w, 0.f);
        *(float4*)&midbuf[ty][tx * 4] = acc;
        __syncwarp();

        float4 a2 = *(float4*)&bias2[tx * 4];
        #pragma unroll 16
        for (int k = 0; k < 64; k++) {
            float  r = midbuf[ty][k];
            float4 w = *(float4*)&Wb[k * 64 + tx * 4];
            a2.x += r * w.x; a2.y += r * w.y;
            a2.z += r * w.z; a2.w += r * w.w;
        }
        a2.x = fmaxf(a2.x, 0.f); a2.y = fmaxf(a2.y, 0.f);
        a2.z = fmaxf(a2.z, 0.f); a2.w = fmaxf(a2.w, 0.f);

        if (valid) {
            *(float4*)(g_h1b  + (size_t)node * 64 + tx * 4) = a2;
            *(float4*)(g_agg2 + (size_t)node * 64 + tx * 4) = a2;
        }
        __syncwarp();
    }
}

// ---------------------------------------------------------------------------
// K5: MLP2 + pooling: h2 = relu(BN(agg2 @ W2 + b2)); xstruct[batch[i]] += h2
// ---------------------------------------------------------------------------
__global__ __launch_bounds__(256) void mlp2_kernel(
    const float* __restrict__ W2, const float* __restrict__ b2,
    const float* __restrict__ g2, const float* __restrict__ be2,
    const float* __restrict__ m2, const float* __restrict__ v2,
    const int* __restrict__ batch)
{
    __shared__ float Ws[64 * 64];
    __shared__ float bias[64], scl[64];
    __shared__ float rowbuf[16][64];

    const int tx = threadIdx.x;
    const int ty = threadIdx.y;
    const int tid = ty * 16 + tx;

    if (tid < 64) {
        float s = g2[tid] * rsqrtf(v2[tid] + BN_EPS);
        scl[tid]  = s;
        bias[tid] = b2[tid] * s + be2[tid] - m2[tid] * s;
    }
    __syncthreads();
    for (int idx = tid; idx < 4096; idx += 256)
        Ws[idx] = W2[idx] * scl[idx & 63];
    __syncthreads();

    for (int n0 = blockIdx.x * 16; n0 < NN; n0 += gridDim.x * 16) {
        int node = n0 + ty;
        bool valid = node < NN;
        if (valid)
            *(float4*)&rowbuf[ty][tx * 4] =
                *(const float4*)(g_agg2 + (size_t)node * 64 + tx * 4);
        __syncwarp();

        float4 acc = *(float4*)&bias[tx * 4];
        #pragma unroll 16
        for (int k = 0; k < 64; k++) {
            float  r = rowbuf[ty][k];
            float4 w = *(float4*)&Ws[k * 64 + tx * 4];
            acc.x += r * w.x; acc.y += r * w.y;
            acc.z += r * w.z; acc.w += r * w.w;
        }
        acc.x = fmaxf(acc.x, 0.f); acc.y = fmaxf(acc.y, 0.f);
        acc.z = fmaxf(acc.z, 0.f); acc.w = fmaxf(acc.w, 0.f);

        if (valid) {
            int g = batch[node];
            red_add_v4(g_xstruct + (size_t)g * 64 + tx * 4, acc);
        }
        __syncwarp();
    }
}

// ---------------------------------------------------------------------------
// K6: x_topo = relu(topo @ Wt + bt); out = [xstruct, x_topo] @ Wc + bc
// blockDim (64,4): tx -> column, ty -> graph within tile of 4.
// ---------------------------------------------------------------------------
__global__ __launch_bounds__(256) void final_kernel(
    const float* __restrict__ topo, const float* __restrict__ Wt,
    const float* __restrict__ bt,   const float* __restrict__ Wc,
    const float* __restrict__ bc,   float* __restrict__ out)
{
    __shared__ float Wts[64 * 64];
    __shared__ float Wcs[128 * CC];
    __shared__ float bts[64], bcs[CC];
    __shared__ float trow[4][64];
    __shared__ float xt[4][64];
    __shared__ float xs[4][64];

    const int tx = threadIdx.x;   // 0..63
    const int ty = threadIdx.y;   // 0..3
    const int tid = ty * 64 + tx;

    for (int i = tid; i < 4096; i += 256) Wts[i] = Wt[i];
    for (int i = tid; i < 128 * CC; i += 256) Wcs[i] = Wc[i];
    if (tid < 64) bts[tid] = bt[tid];
    if (tid < CC) bcs[tid] = bc[tid];
    __syncthreads();

    for (int g0 = blockIdx.x * 4; g0 < BB; g0 += gridDim.x * 4) {
        int g = g0 + ty;
        bool valid = g < BB;
        if (valid) {
            trow[ty][tx] = topo[g * 64 + tx];
            xs[ty][tx]   = g_xstruct[g * 64 + tx];
        }
        __syncthreads();
        if (valid) {
            float acc = bts[tx];
            #pragma unroll 16
            for (int k = 0; k < 64; k++)
                acc += trow[ty][k] * Wts[k * 64 + tx];
            xt[ty][tx] = fmaxf(acc, 0.f);
        }
        __syncthreads();
        if (valid && tx < CC) {
            float acc = bcs[tx];
            #pragma unroll 16
            for (int k = 0; k < 64; k++) {
                acc += xs[ty][k] * Wcs[k * CC + tx];
                acc += xt[ty][k] * Wcs[(64 + k) * CC + tx];
            }
            out[g * CC + tx] = acc;
        }
        __syncthreads();
    }
}

// ---------------------------------------------------------------------------
extern "C" void kernel_launch(void* const* d_in, const int* in_sizes, int n_in,
                              void* d_out, int out_size) {
    const float* x    = (const float*)d_in[0];
    const int*   ei   = (const int*)d_in[1];
    const int*   batch= (const int*)d_in[2];
    const float* topo = (const float*)d_in[3];
    const float* W1a  = (const float*)d_in[4];
    const float* b1a  = (const float*)d_in[5];
    const float* g1   = (const float*)d_in[6];
    const float* be1  = (const float*)d_in[7];
    const float* m1   = (const float*)d_in[8];
    const float* v1   = (const float*)d_in[9];
    const float* W1b  = (const float*)d_in[10];
    const float* b1b  = (const float*)d_in[11];
    const float* W2   = (const float*)d_in[12];
    const float* b2   = (const float*)d_in[13];
    const float* g2   = (const float*)d_in[14];
    const float* be2  = (const float*)d_in[15];
    const float* m2   = (const float*)d_in[16];
    const float* v2   = (const float*)d_in[17];
    const float* Wt   = (const float*)d_in[18];
    const float* bt   = (const float*)d_in[19];
    const float* Wc   = (const float*)d_in[20];
    const float* bc   = (const float*)d_in[21];
    float* out = (float*)d_out;

    dim3 mlpBlock(16, 16);
    dim3 finBlock(64, 4);

    init_kernel<<<(NN * HH + 255) / 256, 256>>>(x);
    edge_agg1_kernel<<<(EE * 16 + 255) / 256, 256>>>(x, ei);
    mlp1_kernel<<<888, mlpBlock>>>(W1a, b1a, g1, be1, m1, v1, W1b, b1b);
    edge_agg2_kernel<<<(EE * 16 + 255) / 256, 256>>>(ei);
    mlp2_kernel<<<888, mlpBlock>>>(W2, b2, g2, be2, m2, v2, batch);
    final_kernel<<<64, finBlock>>>(topo, Wt, bt, Wc, bc, out);
}

// round 2
// speedup vs baseline: 1.3931x; 1.3931x over previous
#include <cuda_runtime.h>

#define NN 100000
#define EE 1200000
#define HH 64
#define BB 1000
#define CC 10
#define BN_EPS 1e-5f
#define PAD 65   // padded row stride in shared buf (floats)

typedef unsigned long long u64;

// Scratch (device globals; no allocation allowed)
__device__ __align__(16) float g_agg1[NN * HH];     // x + scatter(x)
__device__ __align__(16) float g_h1b[NN * HH];      // output of MLP1
__device__ __align__(16) float g_agg2[NN * HH];     // h1b + scatter(h1b)
__device__ __align__(16) float g_xstruct[BB * HH];  // pooled per-graph features

__device__ __forceinline__ void red_add_v4(float* p, float4 v) {
    asm volatile("red.global.add.v4.f32 [%0], {%1,%2,%3,%4};"
                 :: "l"(p), "f"(v.x), "f"(v.y), "f"(v.z), "f"(v.w)
                 : "memory");
}

__device__ __forceinline__ u64 pack2(float lo, float hi) {
    u64 r;
    asm("mov.b64 %0, {%1,%2};" : "=l"(r) : "f"(lo), "f"(hi));
    return r;
}
__device__ __forceinline__ void unpack2(u64 v, float& lo, float& hi) {
    asm("mov.b64 {%0,%1}, %2;" : "=f"(lo), "=f"(hi) : "l"(v));
}
__device__ __forceinline__ void ffma2(u64& d, u64 a, u64 b) {
    asm("fma.rn.f32x2 %0, %1, %2, %0;" : "+l"(d) : "l"(a), "l"(b));
}

// ---------------------------------------------------------------------------
// K1: agg1 = x (self term); xstruct = 0
// ---------------------------------------------------------------------------
__global__ void init_kernel(const float* __restrict__ x) {
    int i = blockIdx.x * 256 + threadIdx.x;
    if (i < NN * HH) g_agg1[i] = x[i];
    if (i < BB * HH) g_xstruct[i] = 0.0f;
}

// ---------------------------------------------------------------------------
// K2: agg1[dst] += x[src]  (16 threads per edge, float4 chunks)
// ---------------------------------------------------------------------------
__global__ void edge_agg1_kernel(const float* __restrict__ x,
                                 const int* __restrict__ ei) {
    int tid = blockIdx.x * 256 + threadIdx.x;
    if (tid >= EE * 16) return;
    int eid = tid >> 4;
    int c   = (tid & 15) * 4;
    int s = ei[eid];
    int d = ei[EE + eid];
    float4 v = *(const float4*)(x + (size_t)s * HH + c);
    red_add_v4(g_agg1 + (size_t)d * HH + c, v);
}

// K4: agg2[dst] += h1b[src]
__global__ void edge_agg2_kernel(const int* __restrict__ ei) {
    int tid = blockIdx.x * 256 + threadIdx.x;
    if (tid >= EE * 16) return;
    int eid = tid >> 4;
    int c   = (tid & 15) * 4;
    int s = ei[eid];
    int d = ei[EE + eid];
    float4 v = *(const float4*)(g_h1b + (size_t)s * HH + c);
    red_add_v4(g_agg2 + (size_t)d * HH + c, v);
}

// ---------------------------------------------------------------------------
// K3: MLP1: h1b = relu( relu(BN(agg1 @ W1a + b1a)) @ W1b + b1b )
//     BN folded into Wa columns + bias. Also seeds agg2 = h1b (self term).
// 128 threads: tx(0..7) -> 8 cols, ty(0..15) -> 8 rows. Tile = 128 nodes.
// Inner loop uses packed fma.rn.f32x2 (FFMA2): 32 FFMA2 per k per thread.
// Dynamic smem: Wa[4096] + Wb[4096] + buf[128*PAD] floats.
// ---------------------------------------------------------------------------
__global__ __launch_bounds__(128) void mlp1_kernel(
    const float* __restrict__ W1a, const float* __restrict__ b1a,
    const float* __restrict__ g1,  const float* __restrict__ be1,
    const float* __restrict__ m1,  const float* __restrict__ v1,
    const float* __restrict__ W1b, const float* __restrict__ b1b)
{
    extern __shared__ float sm[];
    float* Wa  = sm;                 // 4096 floats
    float* Wb  = sm + 4096;          // 4096 floats
    float* buf = sm + 8192;          // 128*PAD floats
    __shared__ float bias1[64], bias2[64], scl[64];

    const int tid = threadIdx.x;
    const int tx  = tid & 7;    // col group: cols tx*8 .. tx*8+7
    const int ty  = tid >> 3;   // row group: rows ty*8 .. ty*8+7

    if (tid < 64) {
        float s = g1[tid] * rsqrtf(v1[tid] + BN_EPS);
        scl[tid]   = s;
        bias1[tid] = b1a[tid] * s + be1[tid] - m1[tid] * s;
        bias2[tid] = b1b[tid];
    }
    __syncthreads();
    for (int i = tid; i < 4096; i += 128) {
        Wa[i] = W1a[i] * scl[i & 63];
        Wb[i] = W1b[i];
    }
    __syncthreads();

    u64 b1p[4], b2p[4];
    #pragma unroll
    for (int c = 0; c < 4; c++) {
        b1p[c] = pack2(bias1[tx * 8 + 2 * c], bias1[tx * 8 + 2 * c + 1]);
        b2p[c] = pack2(bias2[tx * 8 + 2 * c], bias2[tx * 8 + 2 * c + 1]);
    }

    for (int n0 = blockIdx.x * 128; n0 < NN; n0 += gridDim.x * 128) {
        __syncthreads();   // previous tile fully consumed buf

        // Load 128 node rows into buf (row-major, padded)
        for (int i = tid; i < 128 * 16; i += 128) {
            int r = i >> 4, q = i & 15;
            int node = n0 + r;
            float4 v = make_float4(0.f, 0.f, 0.f, 0.f);
            if (node < NN)
                v = *(const float4*)(g_agg1 + (size_t)node * 64 + q * 4);
            float* p = buf + r * PAD + q * 4;
            p[0] = v.x; p[1] = v.y; p[2] = v.z; p[3] = v.w;
        }
        __syncthreads();

        // ---- layer 1 ----
        u64 acc[8][4];
        #pragma unroll
        for (int j = 0; j < 8; j++)
            #pragma unroll
            for (int c = 0; c < 4; c++) acc[j][c] = b1p[c];

        #pragma unroll 8
        for (int k = 0; k < 64; k++) {
            const u64* wr = (const u64*)(Wa + k * 64 + tx * 8);
            u64 w0 = wr[0], w1 = wr[1], w2 = wr[2], w3 = wr[3];
            #pragma unroll
            for (int j = 0; j < 8; j++) {
                float rv = buf[(ty * 8 + j) * PAD + k];
                u64 rp = pack2(rv, rv);
                ffma2(acc[j][0], rp, w0);
                ffma2(acc[j][1], rp, w1);
                ffma2(acc[j][2], rp, w2);
                ffma2(acc[j][3], rp, w3);
            }
        }
        __syncthreads();   // all layer-1 reads of buf done

        // relu + write mid back into buf
        #pragma unroll
        for (int j = 0; j < 8; j++) {
            float* p = buf + (ty * 8 + j) * PAD + tx * 8;
            #pragma unroll
            for (int c = 0; c < 4; c++) {
                float lo, hi;
                unpack2(acc[j][c], lo, hi);
                p[2 * c]     = fmaxf(lo, 0.f);
                p[2 * c + 1] = fmaxf(hi, 0.f);
            }
        }
        __syncthreads();

        // ---- layer 2 ----
        u64 a2[8][4];
        #pragma unroll
        for (int j = 0; j < 8; j++)
            #pragma unroll
            for (int c = 0; c < 4; c++) a2[j][c] = b2p[c];

        #pragma unroll 8
        for (int k = 0; k < 64; k++) {
            const u64* wr = (const u64*)(Wb + k * 64 + tx * 8);
            u64 w0 = wr[0], w1 = wr[1], w2 = wr[2], w3 = wr[3];
            #pragma unroll
            for (int j = 0; j < 8; j++) {
                float rv = buf[(ty * 8 + j) * PAD + k];
                u64 rp = pack2(rv, rv);
                ffma2(a2[j][0], rp, w0);
                ffma2(a2[j][1], rp, w1);
                ffma2(a2[j][2], rp, w2);
                ffma2(a2[j][3], rp, w3);
            }
        }

        // relu + store to g_h1b and g_agg2 (self term seed)
        #pragma unroll
        for (int j = 0; j < 8; j++) {
            int node = n0 + ty * 8 + j;
            if (node >= NN) break;
            float o[8];
            #pragma unroll
            for (int c = 0; c < 4; c++) {
                unpack2(a2[j][c], o[2 * c], o[2 * c + 1]);
                o[2 * c]     = fmaxf(o[2 * c], 0.f);
                o[2 * c + 1] = fmaxf(o[2 * c + 1], 0.f);
            }
            float4 v0 = make_float4(o[0], o[1], o[2], o[3]);
            float4 v1_ = make_float4(o[4], o[5], o[6], o[7]);
            float* d0 = g_h1b  + (size_t)node * 64 + tx * 8;
            float* d1 = g_agg2 + (size_t)node * 64 + tx * 8;
            *(float4*)(d0)     = v0;
            *(float4*)(d0 + 4) = v1_;
            *(float4*)(d1)     = v0;
            *(float4*)(d1 + 4) = v1_;
        }
    }
}

// ---------------------------------------------------------------------------
// K5: MLP2 + pooling: h2 = relu(BN(agg2 @ W2 + b2)); xstruct[batch[i]] += h2
// Same register-tiled scheme, one layer. Dynamic smem: W[4096]+buf[128*PAD].
// ---------------------------------------------------------------------------
__global__ __launch_bounds__(128) void mlp2_kernel(
    const float* __restrict__ W2, const float* __restrict__ b2,
    const float* __restrict__ g2, const float* __restrict__ be2,
    const float* __restrict__ m2, const float* __restrict__ v2,
    const int* __restrict__ batch)
{
    extern __shared__ float sm[];
    float* Ws  = sm;                 // 4096 floats
    float* buf = sm + 4096;          // 128*PAD floats
    __shared__ float bias[64], scl[64];

    const int tid = threadIdx.x;
    const int tx  = tid & 7;
    const int ty  = tid >> 3;

    if (tid < 64) {
        float s = g2[tid] * rsqrtf(v2[tid] + BN_EPS);
        scl[tid]  = s;
        bias[tid] = b2[tid] * s + be2[tid] - m2[tid] * s;
    }
    __syncthreads();
    for (int i = tid; i < 4096; i += 128)
        Ws[i] = W2[i] * scl[i & 63];
    __syncthreads();

    u64 bp[4];
    #pragma unroll
    for (int c = 0; c < 4; c++)
        bp[c] = pack2(bias[tx * 8 + 2 * c], bias[tx * 8 + 2 * c + 1]);

    for (int n0 = blockIdx.x * 128; n0 < NN; n0 += gridDim.x * 128) {
        __syncthreads();

        for (int i = tid; i < 128 * 16; i += 128) {
            int r = i >> 4, q = i & 15;
            int node = n0 + r;
            float4 v = make_float4(0.f, 0.f, 0.f, 0.f);
            if (node < NN)
                v = *(const float4*)(g_agg2 + (size_t)node * 64 + q * 4);
            float* p = buf + r * PAD + q * 4;
            p[0] = v.x; p[1] = v.y; p[2] = v.z; p[3] = v.w;
        }
        __syncthreads();

        u64 acc[8][4];
        #pragma unroll
        for (int j = 0; j < 8; j++)
            #pragma unroll
            for (int c = 0; c < 4; c++) acc[j][c] = bp[c];

        #pragma unroll 8
        for (int k = 0; k < 64; k++) {
            const u64* wr = (const u64*)(Ws + k * 64 + tx * 8);
            u64 w0 = wr[0], w1 = wr[1], w2 = wr[2], w3 = wr[3];
            #pragma unroll
            for (int j = 0; j < 8; j++) {
                float rv = buf[(ty * 8 + j) * PAD + k];
                u64 rp = pack2(rv, rv);
                ffma2(acc[j][0], rp, w0);
                ffma2(acc[j][1], rp, w1);
                ffma2(acc[j][2], rp, w2);
                ffma2(acc[j][3], rp, w3);
            }
        }

        #pragma unroll
        for (int j = 0; j < 8; j++) {
            int node = n0 + ty * 8 + j;
            if (node >= NN) break;
            float o[8];
            #pragma unroll
            for (int c = 0; c < 4; c++) {
                unpack2(acc[j][c], o[2 * c], o[2 * c + 1]);
                o[2 * c]     = fmaxf(o[2 * c], 0.f);
                o[2 * c + 1] = fmaxf(o[2 * c + 1], 0.f);
            }
            int g = batch[node];
            float* dst = g_xstruct + (size_t)g * 64 + tx * 8;
            red_add_v4(dst,     make_float4(o[0], o[1], o[2], o[3]));
            red_add_v4(dst + 4, make_float4(o[4], o[5], o[6], o[7]));
        }
    }
}

// ---------------------------------------------------------------------------
// K6: x_topo = relu(topo @ Wt + bt); out = [xstruct, x_topo] @ Wc + bc
// ---------------------------------------------------------------------------
__global__ __launch_bounds__(256) void final_kernel(
    const float* __restrict__ topo, const float* __restrict__ Wt,
    const float* __restrict__ bt,   const float* __restrict__ Wc,
    const float* __restrict__ bc,   float* __restrict__ out)
{
    __shared__ float Wts[64 * 64];
    __shared__ float Wcs[128 * CC];
    __shared__ float bts[64], bcs[CC];
    __shared__ float trow[4][64];
    __shared__ float xt[4][64];
    __shared__ float xs[4][64];

    const int tx = threadIdx.x;   // 0..63
    const int ty = threadIdx.y;   // 0..3
    const int tid = ty * 64 + tx;

    for (int i = tid; i < 4096; i += 256) Wts[i] = Wt[i];
    for (int i = tid; i < 128 * CC; i += 256) Wcs[i] = Wc[i];
    if (tid < 64) bts[tid] = bt[tid];
    if (tid < CC) bcs[tid] = bc[tid];
    __syncthreads();

    for (int g0 = blockIdx.x * 4; g0 < BB; g0 += gridDim.x * 4) {
        int g = g0 + ty;
        bool valid = g < BB;
        if (valid) {
            trow[ty][tx] = topo[g * 64 + tx];
            xs[ty][tx]   = g_xstruct[g * 64 + tx];
        }
        __syncthreads();
        if (valid) {
            float acc = bts[tx];
            #pragma unroll 16
            for (int k = 0; k < 64; k++)
                acc += trow[ty][k] * Wts[k * 64 + tx];
            xt[ty][tx] = fmaxf(acc, 0.f);
        }
        __syncthreads();
        if (valid && tx < CC) {
            float acc = bcs[tx];
            #pragma unroll 16
            for (int k = 0; k < 64; k++) {
                acc += xs[ty][k] * Wcs[k * CC + tx];
                acc += xt[ty][k] * Wcs[(64 + k) * CC + tx];
            }
            out[g * CC + tx] = acc;
        }
        __syncthreads();
    }
}

// ---------------------------------------------------------------------------
extern "C" void kernel_launch(void* const* d_in, const int* in_sizes, int n_in,
                              void* d_out, int out_size) {
    const float* x    = (const float*)d_in[0];
    const int*   ei   = (const int*)d_in[1];
    const int*   batch= (const int*)d_in[2];
    const float* topo = (const float*)d_in[3];
    const float* W1a  = (const float*)d_in[4];
    const float* b1a  = (const float*)d_in[5];
    const float* g1   = (const float*)d_in[6];
    const float* be1  = (const float*)d_in[7];
    const float* m1   = (const float*)d_in[8];
    const float* v1   = (const float*)d_in[9];
    const float* W1b  = (const float*)d_in[10];
    const float* b1b  = (const float*)d_in[11];
    const float* W2   = (const float*)d_in[12];
    const float* b2   = (const float*)d_in[13];
    const float* g2   = (const float*)d_in[14];
    const float* be2  = (const float*)d_in[15];
    const float* m2   = (const float*)d_in[16];
    const float* v2   = (const float*)d_in[17];
    const float* Wt   = (const float*)d_in[18];
    const float* bt   = (const float*)d_in[19];
    const float* Wc   = (const float*)d_in[20];
    const float* bc   = (const float*)d_in[21];
    float* out = (float*)d_out;

    const int smem1 = (4096 + 4096 + 128 * PAD) * (int)sizeof(float);  // ~66 KB
    const int smem2 = (4096 + 128 * PAD) * (int)sizeof(float);         // ~50 KB
    static bool attr_set = false;
    if (!attr_set) {
        cudaFuncSetAttribute(mlp1_kernel,
                             cudaFuncAttributeMaxDynamicSharedMemorySize, smem1);
        cudaFuncSetAttribute(mlp2_kernel,
                             cudaFuncAttributeMaxDynamicSharedMemorySize, smem2);
        attr_set = true;
    }

    dim3 finBlock(64, 4);

    init_kernel<<<(NN * HH + 255) / 256, 256>>>(x);
    edge_agg1_kernel<<<(EE * 16 + 255) / 256, 256>>>(x, ei);
    mlp1_kernel<<<444, 128, smem1>>>(W1a, b1a, g1, be1, m1, v1, W1b, b1b);
    edge_agg2_kernel<<<(EE * 16 + 255) / 256, 256>>>(ei);
    mlp2_kernel<<<444, 128, smem2>>>(W2, b2, g2, be2, m2, v2, batch);
    final_kernel<<<64, finBlock>>>(topo, Wt, bt, Wc, bc, out);
}

// round 4
// speedup vs baseline: 1.8445x; 1.3240x over previous
#include <cuda_runtime.h>

#define NN 100000
#define EE 1200000
#define HH 64
#define BB 1000
#define CC 10
#define BN_EPS 1e-5f
#define PAD 65   // padded row stride in shared buf (floats)

typedef unsigned long long u64;

// Scratch (device globals; no allocation allowed)
__device__ __align__(16) float g_agg1[NN * HH];     // x + scatter(x)
__device__ __align__(16) float g_h1b[NN * HH];      // output of MLP1
__device__ __align__(16) float g_agg2[NN * HH];     // h1b + scatter(h1b)
__device__ __align__(16) float g_xstruct[BB * HH];  // pooled per-graph features
__device__ int g_deg[NN];
__device__ int g_rowptr[NN + 1];
__device__ int g_cursor[NN];
__device__ int g_bsum[512];
__device__ int g_csr[EE];

__device__ __forceinline__ void red_add_v4(float* p, float4 v) {
    asm volatile("red.global.add.v4.f32 [%0], {%1,%2,%3,%4};"
                 :: "l"(p), "f"(v.x), "f"(v.y), "f"(v.z), "f"(v.w)
                 : "memory");
}

__device__ __forceinline__ u64 pack2(float lo, float hi) {
    u64 r;
    asm("mov.b64 %0, {%1,%2};" : "=l"(r) : "f"(lo), "f"(hi));
    return r;
}
__device__ __forceinline__ void unpack2(u64 v, float& lo, float& hi) {
    asm("mov.b64 {%0,%1}, %2;" : "=f"(lo), "=f"(hi) : "l"(v));
}
__device__ __forceinline__ void ffma2(u64& d, u64 a, u64 b) {
    asm("fma.rn.f32x2 %0, %1, %2, %0;" : "+l"(d) : "l"(a), "l"(b));
}

// ---------------------------------------------------------------------------
// CSR build: zero -> hist -> block sums -> scan of block sums -> rowptr ->
// scatter. All int work, tiny vs. the fp traffic.
// ---------------------------------------------------------------------------
__global__ void zero_kernel() {
    int i = blockIdx.x * 256 + threadIdx.x;
    if (i < NN) g_deg[i] = 0;
    if (i < BB * HH) g_xstruct[i] = 0.0f;
}

__global__ void hist_kernel(const int* __restrict__ ei) {
    int e = blockIdx.x * 256 + threadIdx.x;
    if (e < EE) atomicAdd(&g_deg[ei[EE + e]], 1);
}

__global__ void bsum_kernel() {   // 391 blocks x 256
    __shared__ int sh[256];
    int i = blockIdx.x * 256 + threadIdx.x;
    int t = threadIdx.x;
    sh[t] = (i < NN) ? g_deg[i] : 0;
    __syncthreads();
    for (int off = 128; off > 0; off >>= 1) {
        if (t < off) sh[t] += sh[t + off];
        __syncthreads();
    }
    if (t == 0) g_bsum[blockIdx.x] = sh[0];
}

__global__ void bscan_kernel(int nb) {   // 1 block x 512, exclusive scan
    __shared__ int sh[512];
    int t = threadIdx.x;
    sh[t] = (t < nb) ? g_bsum[t] : 0;
    __syncthreads();
    for (int off = 1; off < 512; off <<= 1) {
        int a = (t >= off) ? sh[t - off] : 0;
        __syncthreads();
        sh[t] += a;
        __syncthreads();
    }
    g_bsum[t] = (t > 0) ? sh[t - 1] : 0;
}

__global__ void rowptr_kernel() {   // 391 blocks x 256
    __shared__ int sh[256];
    int i = blockIdx.x * 256 + threadIdx.x;
    int t = threadIdx.x;
    int v = (i < NN) ? g_deg[i] : 0;
    sh[t] = v;
    __syncthreads();
    for (int off = 1; off < 256; off <<= 1) {
        int a = (t >= off) ? sh[t - off] : 0;
        __syncthreads();
        sh[t] += a;
        __syncthreads();
    }
    if (i < NN) {
        int r = g_bsum[blockIdx.x] + sh[t] - v;   // exclusive
        g_rowptr[i] = r;
        g_cursor[i] = r;
    }
    if (i == 0) g_rowptr[NN] = EE;
}

__global__ void scatter_kernel(const int* __restrict__ ei) {
    int e = blockIdx.x * 256 + threadIdx.x;
    if (e < EE) {
        int s = ei[e];
        int d = ei[EE + e];
        int pos = atomicAdd(&g_cursor[d], 1);
        g_csr[pos] = s;
    }
}

// ---------------------------------------------------------------------------
// Pull aggregation: dst[node] = src[node] + sum_{j in N(node)} src[j]
// 16 threads per node, each owns one float4 column chunk. No atomics.
// Globals referenced from device code (NOT passed from host - device symbols
// are not valid host-side pointers).
// ---------------------------------------------------------------------------
__global__ __launch_bounds__(256) void agg1_csr_kernel(const float* __restrict__ x)
{
    int tid = blockIdx.x * 256 + threadIdx.x;
    int node = tid >> 4;
    if (node >= NN) return;
    int c = (tid & 15) * 4;

    float4 acc = *(const float4*)(x + (size_t)node * 64 + c);
    int j = g_rowptr[node];
    int e = g_rowptr[node + 1];
    for (; j + 1 < e; j += 2) {
        int s0 = g_csr[j], s1 = g_csr[j + 1];
        float4 a = *(const float4*)(x + (size_t)s0 * 64 + c);
        float4 b = *(const float4*)(x + (size_t)s1 * 64 + c);
        acc.x += a.x + b.x; acc.y += a.y + b.y;
        acc.z += a.z + b.z; acc.w += a.w + b.w;
    }
    if (j < e) {
        int s0 = g_csr[j];
        float4 a = *(const float4*)(x + (size_t)s0 * 64 + c);
        acc.x += a.x; acc.y += a.y; acc.z += a.z; acc.w += a.w;
    }
    *(float4*)(g_agg1 + (size_t)node * 64 + c) = acc;
}

__global__ __launch_bounds__(256) void agg2_csr_kernel()
{
    int tid = blockIdx.x * 256 + threadIdx.x;
    int node = tid >> 4;
    if (node >= NN) return;
    int c = (tid & 15) * 4;

    const float* src = g_h1b;
    float4 acc = *(const float4*)(src + (size_t)node * 64 + c);
    int j = g_rowptr[node];
    int e = g_rowptr[node + 1];
    for (; j + 1 < e; j += 2) {
        int s0 = g_csr[j], s1 = g_csr[j + 1];
        float4 a = *(const float4*)(src + (size_t)s0 * 64 + c);
        float4 b = *(const float4*)(src + (size_t)s1 * 64 + c);
        acc.x += a.x + b.x; acc.y += a.y + b.y;
        acc.z += a.z + b.z; acc.w += a.w + b.w;
    }
    if (j < e) {
        int s0 = g_csr[j];
        float4 a = *(const float4*)(src + (size_t)s0 * 64 + c);
        acc.x += a.x; acc.y += a.y; acc.z += a.z; acc.w += a.w;
    }
    *(float4*)(g_agg2 + (size_t)node * 64 + c) = acc;
}

// ---------------------------------------------------------------------------
// K3: MLP1: h1b = relu( relu(BN(agg1 @ W1a + b1a)) @ W1b + b1b )
// ---------------------------------------------------------------------------
__global__ __launch_bounds__(128) void mlp1_kernel(
    const float* __restrict__ W1a, const float* __restrict__ b1a,
    const float* __restrict__ g1,  const float* __restrict__ be1,
    const float* __restrict__ m1,  const float* __restrict__ v1,
    const float* __restrict__ W1b, const float* __restrict__ b1b)
{
    extern __shared__ float sm[];
    float* Wa  = sm;                 // 4096 floats
    float* Wb  = sm + 4096;          // 4096 floats
    float* buf = sm + 8192;          // 128*PAD floats
    __shared__ float bias1[64], bias2[64], scl[64];

    const int tid = threadIdx.x;
    const int tx  = tid & 7;    // col group: cols tx*8 .. tx*8+7
    const int ty  = tid >> 3;   // row group: rows ty*8 .. ty*8+7

    if (tid < 64) {
        float s = g1[tid] * rsqrtf(v1[tid] + BN_EPS);
        scl[tid]   = s;
        bias1[tid] = b1a[tid] * s + be1[tid] - m1[tid] * s;
        bias2[tid] = b1b[tid];
    }
    __syncthreads();
    for (int i = tid; i < 4096; i += 128) {
        Wa[i] = W1a[i] * scl[i & 63];
        Wb[i] = W1b[i];
    }
    __syncthreads();

    u64 b1p[4], b2p[4];
    #pragma unroll
    for (int c = 0; c < 4; c++) {
        b1p[c] = pack2(bias1[tx * 8 + 2 * c], bias1[tx * 8 + 2 * c + 1]);
        b2p[c] = pack2(bias2[tx * 8 + 2 * c], bias2[tx * 8 + 2 * c + 1]);
    }

    for (int n0 = blockIdx.x * 128; n0 < NN; n0 += gridDim.x * 128) {
        __syncthreads();

        for (int i = tid; i < 128 * 16; i += 128) {
            int r = i >> 4, q = i & 15;
            int node = n0 + r;
            float4 v = make_float4(0.f, 0.f, 0.f, 0.f);
            if (node < NN)
                v = *(const float4*)(g_agg1 + (size_t)node * 64 + q * 4);
            float* p = buf + r * PAD + q * 4;
            p[0] = v.x; p[1] = v.y; p[2] = v.z; p[3] = v.w;
        }
        __syncthreads();

        // ---- layer 1 ----
        u64 acc[8][4];
        #pragma unroll
        for (int j = 0; j < 8; j++)
            #pragma unroll
            for (int c = 0; c < 4; c++) acc[j][c] = b1p[c];

        #pragma unroll 8
        for (int k = 0; k < 64; k++) {
            const u64* wr = (const u64*)(Wa + k * 64 + tx * 8);
            u64 w0 = wr[0], w1 = wr[1], w2 = wr[2], w3 = wr[3];
            #pragma unroll
            for (int j = 0; j < 8; j++) {
                float rv = buf[(ty * 8 + j) * PAD + k];
                u64 rp = pack2(rv, rv);
                ffma2(acc[j][0], rp, w0);
                ffma2(acc[j][1], rp, w1);
                ffma2(acc[j][2], rp, w2);
                ffma2(acc[j][3], rp, w3);
            }
        }
        __syncthreads();

        #pragma unroll
        for (int j = 0; j < 8; j++) {
            float* p = buf + (ty * 8 + j) * PAD + tx * 8;
            #pragma unroll
            for (int c = 0; c < 4; c++) {
                float lo, hi;
                unpack2(acc[j][c], lo, hi);
                p[2 * c]     = fmaxf(lo, 0.f);
                p[2 * c + 1] = fmaxf(hi, 0.f);
            }
        }
        __syncthreads();

        // ---- layer 2 ----
        u64 a2[8][4];
        #pragma unroll
        for (int j = 0; j < 8; j++)
            #pragma unroll
            for (int c = 0; c < 4; c++) a2[j][c] = b2p[c];

        #pragma unroll 8
        for (int k = 0; k < 64; k++) {
            const u64* wr = (const u64*)(Wb + k * 64 + tx * 8);
            u64 w0 = wr[0], w1 = wr[1], w2 = wr[2], w3 = wr[3];
            #pragma unroll
            for (int j = 0; j < 8; j++) {
                float rv = buf[(ty * 8 + j) * PAD + k];
                u64 rp = pack2(rv, rv);
                ffma2(a2[j][0], rp, w0);
                ffma2(a2[j][1], rp, w1);
                ffma2(a2[j][2], rp, w2);
                ffma2(a2[j][3], rp, w3);
            }
        }

        #pragma unroll
        for (int j = 0; j < 8; j++) {
            int node = n0 + ty * 8 + j;
            if (node >= NN) break;
            float o[8];
            #pragma unroll
            for (int c = 0; c < 4; c++) {
                unpack2(a2[j][c], o[2 * c], o[2 * c + 1]);
                o[2 * c]     = fmaxf(o[2 * c], 0.f);
                o[2 * c + 1] = fmaxf(o[2 * c + 1], 0.f);
            }
            float* d0 = g_h1b + (size_t)node * 64 + tx * 8;
            *(float4*)(d0)     = make_float4(o[0], o[1], o[2], o[3]);
            *(float4*)(d0 + 4) = make_float4(o[4], o[5], o[6], o[7]);
        }
    }
}

// ---------------------------------------------------------------------------
// K5: MLP2 + pooling: h2 = relu(BN(agg2 @ W2 + b2)); xstruct[batch[i]] += h2
// ---------------------------------------------------------------------------
__global__ __launch_bounds__(128) void mlp2_kernel(
    const float* __restrict__ W2, const float* __restrict__ b2,
    const float* __restrict__ g2, const float* __restrict__ be2,
    const float* __restrict__ m2, const float* __restrict__ v2,
    const int* __restrict__ batch)
{
    extern __shared__ float sm[];
    float* Ws  = sm;                 // 4096 floats
    float* buf = sm + 4096;          // 128*PAD floats
    __shared__ float bias[64], scl[64];

    const int tid = threadIdx.x;
    const int tx  = tid & 7;
    const int ty  = tid >> 3;

    if (tid < 64) {
        float s = g2[tid] * rsqrtf(v2[tid] + BN_EPS);
        scl[tid]  = s;
        bias[tid] = b2[tid] * s + be2[tid] - m2[tid] * s;
    }
    __syncthreads();
    for (int i = tid; i < 4096; i += 128)
        Ws[i] = W2[i] * scl[i & 63];
    __syncthreads();

    u64 bp[4];
    #pragma unroll
    for (int c = 0; c < 4; c++)
        bp[c] = pack2(bias[tx * 8 + 2 * c], bias[tx * 8 + 2 * c + 1]);

    for (int n0 = blockIdx.x * 128; n0 < NN; n0 += gridDim.x * 128) {
        __syncthreads();

        for (int i = tid; i < 128 * 16; i += 128) {
            int r = i >> 4, q = i & 15;
            int node = n0 + r;
            float4 v = make_float4(0.f, 0.f, 0.f, 0.f);
            if (node < NN)
                v = *(const float4*)(g_agg2 + (size_t)node * 64 + q * 4);
            float* p = buf + r * PAD + q * 4;
            p[0] = v.x; p[1] = v.y; p[2] = v.z; p[3] = v.w;
        }
        __syncthreads();

        u64 acc[8][4];
        #pragma unroll
        for (int j = 0; j < 8; j++)
            #pragma unroll
            for (int c = 0; c < 4; c++) acc[j][c] = bp[c];

        #pragma unroll 8
        for (int k = 0; k < 64; k++) {
            const u64* wr = (const u64*)(Ws + k * 64 + tx * 8);
            u64 w0 = wr[0], w1 = wr[1], w2 = wr[2], w3 = wr[3];
            #pragma unroll
            for (int j = 0; j < 8; j++) {
                float rv = buf[(ty * 8 + j) * PAD + k];
                u64 rp = pack2(rv, rv);
                ffma2(acc[j][0], rp, w0);
                ffma2(acc[j][1], rp, w1);
                ffma2(acc[j][2], rp, w2);
                ffma2(acc[j][3], rp, w3);
            }
        }

        #pragma unroll
        for (int j = 0; j < 8; j++) {
            int node = n0 + ty * 8 + j;
            if (node >= NN) break;
            float o[8];
            #pragma unroll
            for (int c = 0; c < 4; c++) {
                unpack2(acc[j][c], o[2 * c], o[2 * c + 1]);
                o[2 * c]     = fmaxf(o[2 * c], 0.f);
                o[2 * c + 1] = fmaxf(o[2 * c + 1], 0.f);
            }
            int g = batch[node];
            float* dst = g_xstruct + (size_t)g * 64 + tx * 8;
            red_add_v4(dst,     make_float4(o[0], o[1], o[2], o[3]));
            red_add_v4(dst + 4, make_float4(o[4], o[5], o[6], o[7]));
        }
    }
}

// ---------------------------------------------------------------------------
// K6: x_topo = relu(topo @ Wt + bt); out = [xstruct, x_topo] @ Wc + bc
// ---------------------------------------------------------------------------
__global__ __launch_bounds__(256) void final_kernel(
    const float* __restrict__ topo, const float* __restrict__ Wt,
    const float* __restrict__ bt,   const float* __restrict__ Wc,
    const float* __restrict__ bc,   float* __restrict__ out)
{
    __shared__ float Wts[64 * 64];
    __shared__ float Wcs[128 * CC];
    __shared__ float bts[64], bcs[CC];
    __shared__ float trow[4][64];
    __shared__ float xt[4][64];
    __shared__ float xs[4][64];

    const int tx = threadIdx.x;   // 0..63
    const int ty = threadIdx.y;   // 0..3
    const int tid = ty * 64 + tx;

    for (int i = tid; i < 4096; i += 256) Wts[i] = Wt[i];
    for (int i = tid; i < 128 * CC; i += 256) Wcs[i] = Wc[i];
    if (tid < 64) bts[tid] = bt[tid];
    if (tid < CC) bcs[tid] = bc[tid];
    __syncthreads();

    for (int g0 = blockIdx.x * 4; g0 < BB; g0 += gridDim.x * 4) {
        int g = g0 + ty;
        bool valid = g < BB;
        if (valid) {
            trow[ty][tx] = topo[g * 64 + tx];
            xs[ty][tx]   = g_xstruct[g * 64 + tx];
        }
        __syncthreads();
        if (valid) {
            float acc = bts[tx];
            #pragma unroll 16
            for (int k = 0; k < 64; k++)
                acc += trow[ty][k] * Wts[k * 64 + tx];
            xt[ty][tx] = fmaxf(acc, 0.f);
        }
        __syncthreads();
        if (valid && tx < CC) {
            float acc = bcs[tx];
            #pragma unroll 16
            for (int k = 0; k < 64; k++) {
                acc += xs[ty][k] * Wcs[k * CC + tx];
                acc += xt[ty][k] * Wcs[(64 + k) * CC + tx];
            }
            out[g * CC + tx] = acc;
        }
        __syncthreads();
    }
}

// ---------------------------------------------------------------------------
extern "C" void kernel_launch(void* const* d_in, const int* in_sizes, int n_in,
                              void* d_out, int out_size) {
    const float* x    = (const float*)d_in[0];
    const int*   ei   = (const int*)d_in[1];
    const int*   batch= (const int*)d_in[2];
    const float* topo = (const float*)d_in[3];
    const float* W1a  = (const float*)d_in[4];
    const float* b1a  = (const float*)d_in[5];
    const float* g1   = (const float*)d_in[6];
    const float* be1  = (const float*)d_in[7];
    const float* m1   = (const float*)d_in[8];
    const float* v1   = (const float*)d_in[9];
    const float* W1b  = (const float*)d_in[10];
    const float* b1b  = (const float*)d_in[11];
    const float* W2   = (const float*)d_in[12];
    const float* b2   = (const float*)d_in[13];
    const float* g2   = (const float*)d_in[14];
    const float* be2  = (const float*)d_in[15];
    const float* m2   = (const float*)d_in[16];
    const float* v2   = (const float*)d_in[17];
    const float* Wt   = (const float*)d_in[18];
    const float* bt   = (const float*)d_in[19];
    const float* Wc   = (const float*)d_in[20];
    const float* bc   = (const float*)d_in[21];
    float* out = (float*)d_out;

    const int smem1 = (4096 + 4096 + 128 * PAD) * (int)sizeof(float);  // ~66 KB
    const int smem2 = (4096 + 128 * PAD) * (int)sizeof(float);         // ~50 KB
    static bool attr_set = false;
    if (!attr_set) {
        cudaFuncSetAttribute(mlp1_kernel,
                             cudaFuncAttributeMaxDynamicSharedMemorySize, smem1);
        cudaFuncSetAttribute(mlp2_kernel,
                             cudaFuncAttributeMaxDynamicSharedMemorySize, smem2);
        attr_set = true;
    }

    const int NB = (NN + 255) / 256;         // 391
    dim3 finBlock(64, 4);

    // CSR build
    zero_kernel<<<NB, 256>>>();
    hist_kernel<<<(EE + 255) / 256, 256>>>(ei);
    bsum_kernel<<<NB, 256>>>();
    bscan_kernel<<<1, 512>>>(NB);
    rowptr_kernel<<<NB, 256>>>();
    scatter_kernel<<<(EE + 255) / 256, 256>>>(ei);

    // Layer 1
    agg1_csr_kernel<<<(NN * 16 + 255) / 256, 256>>>(x);
    mlp1_kernel<<<444, 128, smem1>>>(W1a, b1a, g1, be1, m1, v1, W1b, b1b);

    // Layer 2
    agg2_csr_kernel<<<(NN * 16 + 255) / 256, 256>>>();
    mlp2_kernel<<<444, 128, smem2>>>(W2, b2, g2, be2, m2, v2, batch);

    final_kernel<<<64, finBlock>>>(topo, Wt, bt, Wc, bc, out);
}

// round 5
// speedup vs baseline: 1.9785x; 1.0726x over previous
#include <cuda_runtime.h>
#include <cuda_fp16.h>

#define NN 100000
#define EE 1200000
#define HH 64
#define BB 1000
#define CC 10
#define BN_EPS 1e-5f
#define PAD 65   // padded row stride in shared buf (floats)

typedef unsigned long long u64;

// Scratch (device globals; no allocation allowed)
__device__ __align__(16) float  g_agg1[NN * HH];     // x + scatter(x)  (fp32)
__device__ __align__(16) float  g_agg2[NN * HH];     // h1b + scatter(h1b)
__device__ __align__(16) __half g_xh[NN * HH];       // fp16 shadow of x
__device__ __align__(16) __half g_h1bh[NN * HH];     // fp16 output of MLP1
__device__ __align__(16) float  g_xstruct[BB * HH];  // pooled per-graph features
__device__ int g_deg[NN];
__device__ int g_rowptr[NN + 1];
__device__ int g_cursor[NN];
__device__ int g_bsum[512];
__device__ int g_csr[EE];

__device__ __forceinline__ void red_add_v4(float* p, float4 v) {
    asm volatile("red.global.add.v4.f32 [%0], {%1,%2,%3,%4};"
                 :: "l"(p), "f"(v.x), "f"(v.y), "f"(v.z), "f"(v.w)
                 : "memory");
}

__device__ __forceinline__ u64 pack2(float lo, float hi) {
    u64 r;
    asm("mov.b64 %0, {%1,%2};" : "=l"(r) : "f"(lo), "f"(hi));
    return r;
}
__device__ __forceinline__ void unpack2(u64 v, float& lo, float& hi) {
    asm("mov.b64 {%0,%1}, %2;" : "=f"(lo), "=f"(hi) : "l"(v));
}
__device__ __forceinline__ void ffma2(u64& d, u64 a, u64 b) {
    asm("fma.rn.f32x2 %0, %1, %2, %0;" : "+l"(d) : "l"(a), "l"(b));
}

// ---------------------------------------------------------------------------
// Prep: zero deg + xstruct, convert x -> fp16 shadow table.
// Grid covers NN*HH/4 = 1.6M threads (float4 -> half4 per thread).
// ---------------------------------------------------------------------------
__global__ void prep_kernel(const float* __restrict__ x) {
    int i = blockIdx.x * 256 + threadIdx.x;
    if (i < NN) g_deg[i] = 0;
    if (i < BB * HH) g_xstruct[i] = 0.0f;
    if (i < NN * HH / 4) {
        float4 v = *(const float4*)(x + (size_t)i * 4);
        __half2 h0 = __floats2half2_rn(v.x, v.y);
        __half2 h1 = __floats2half2_rn(v.z, v.w);
        uint2 u;
        u.x = *(unsigned*)&h0;
        u.y = *(unsigned*)&h1;
        *(uint2*)(g_xh + (size_t)i * 4) = u;
    }
}

__global__ void hist_kernel(const int* __restrict__ ei) {
    int e = blockIdx.x * 256 + threadIdx.x;
    if (e < EE) atomicAdd(&g_deg[ei[EE + e]], 1);
}

__global__ void bsum_kernel() {   // 391 blocks x 256, raw block sums
    __shared__ int sh[256];
    int i = blockIdx.x * 256 + threadIdx.x;
    int t = threadIdx.x;
    sh[t] = (i < NN) ? g_deg[i] : 0;
    __syncthreads();
    for (int off = 128; off > 0; off >>= 1) {
        if (t < off) sh[t] += sh[t + off];
        __syncthreads();
    }
    if (t == 0) g_bsum[blockIdx.x] = sh[0];
}

// rowptr: inline prefix over raw block sums (replaces separate bscan kernel)
__global__ void rowptr_kernel() {   // 391 blocks x 256
    __shared__ int sh[256];
    __shared__ int red[256];
    int i = blockIdx.x * 256 + threadIdx.x;
    int t = threadIdx.x;

    // block-global offset = sum of bsum[0..blockIdx)
    int pre = 0;
    for (int b = t; b < blockIdx.x; b += 256) pre += g_bsum[b];
    red[t] = pre;
    __syncthreads();
    for (int off = 128; off > 0; off >>= 1) {
        if (t < off) red[t] += red[t + off];
        __syncthreads();
    }
    int base = red[0];

    int v = (i < NN) ? g_deg[i] : 0;
    sh[t] = v;
    __syncthreads();
    for (int off = 1; off < 256; off <<= 1) {
        int a = (t >= off) ? sh[t - off] : 0;
        __syncthreads();
        sh[t] += a;
        __syncthreads();
    }
    if (i < NN) {
        int r = base + sh[t] - v;   // exclusive
        g_rowptr[i] = r;
        g_cursor[i] = r;
    }
    if (i == 0) g_rowptr[NN] = EE;
}

__global__ void scatter_kernel(const int* __restrict__ ei) {
    int e = blockIdx.x * 256 + threadIdx.x;
    if (e < EE) {
        int s = ei[e];
        int d = ei[EE + e];
        int pos = atomicAdd(&g_cursor[d], 1);
        g_csr[pos] = s;
    }
}

// ---------------------------------------------------------------------------
// Pull aggregation, fp16 neighbor gather, fp32 accumulate.
// 16 threads per node, each owns 4 columns (8 B fp16 per row). No atomics.
// ---------------------------------------------------------------------------
__device__ __forceinline__ void acc_half4(float4& acc, const __half* base) {
    uint2 u = *(const uint2*)base;
    __half2 h0 = *(__half2*)&u.x;
    __half2 h1 = *(__half2*)&u.y;
    float2 f0 = __half22float2(h0);
    float2 f1 = __half22float2(h1);
    acc.x += f0.x; acc.y += f0.y; acc.z += f1.x; acc.w += f1.y;
}

__global__ __launch_bounds__(256) void agg1_kernel(const float* __restrict__ x)
{
    int tid = blockIdx.x * 256 + threadIdx.x;
    int node = tid >> 4;
    if (node >= NN) return;
    int c = (tid & 15) * 4;

    // self term exact fp32
    float4 acc = *(const float4*)(x + (size_t)node * 64 + c);
    int j = g_rowptr[node];
    int e = g_rowptr[node + 1];
    for (; j + 1 < e; j += 2) {
        int s0 = g_csr[j], s1 = g_csr[j + 1];
        acc_half4(acc, g_xh + (size_t)s0 * 64 + c);
        acc_half4(acc, g_xh + (size_t)s1 * 64 + c);
    }
    if (j < e) {
        int s0 = g_csr[j];
        acc_half4(acc, g_xh + (size_t)s0 * 64 + c);
    }
    *(float4*)(g_agg1 + (size_t)node * 64 + c) = acc;
}

__global__ __launch_bounds__(256) void agg2_kernel()
{
    int tid = blockIdx.x * 256 + threadIdx.x;
    int node = tid >> 4;
    if (node >= NN) return;
    int c = (tid & 15) * 4;

    float4 acc = make_float4(0.f, 0.f, 0.f, 0.f);
    acc_half4(acc, g_h1bh + (size_t)node * 64 + c);   // self
    int j = g_rowptr[node];
    int e = g_rowptr[node + 1];
    for (; j + 1 < e; j += 2) {
        int s0 = g_csr[j], s1 = g_csr[j + 1];
        acc_half4(acc, g_h1bh + (size_t)s0 * 64 + c);
        acc_half4(acc, g_h1bh + (size_t)s1 * 64 + c);
    }
    if (j < e) {
        int s0 = g_csr[j];
        acc_half4(acc, g_h1bh + (size_t)s0 * 64 + c);
    }
    *(float4*)(g_agg2 + (size_t)node * 64 + c) = acc;
}

// ---------------------------------------------------------------------------
// K3: MLP1: h1bh = fp16( relu( relu(BN(agg1 @ W1a + b1a)) @ W1b + b1b ) )
// ---------------------------------------------------------------------------
__global__ __launch_bounds__(128) void mlp1_kernel(
    const float* __restrict__ W1a, const float* __restrict__ b1a,
    const float* __restrict__ g1,  const float* __restrict__ be1,
    const float* __restrict__ m1,  const float* __restrict__ v1,
    const float* __restrict__ W1b, const float* __restrict__ b1b)
{
    extern __shared__ float sm[];
    float* Wa  = sm;                 // 4096 floats
    float* Wb  = sm + 4096;          // 4096 floats
    float* buf = sm + 8192;          // 128*PAD floats
    __shared__ float bias1[64], bias2[64], scl[64];

    const int tid = threadIdx.x;
    const int tx  = tid & 7;    // col group: cols tx*8 .. tx*8+7
    const int ty  = tid >> 3;   // row group: rows ty*8 .. ty*8+7

    if (tid < 64) {
        float s = g1[tid] * rsqrtf(v1[tid] + BN_EPS);
        scl[tid]   = s;
        bias1[tid] = b1a[tid] * s + be1[tid] - m1[tid] * s;
        bias2[tid] = b1b[tid];
    }
    __syncthreads();
    for (int i = tid; i < 4096; i += 128) {
        Wa[i] = W1a[i] * scl[i & 63];
        Wb[i] = W1b[i];
    }
    __syncthreads();

    u64 b1p[4], b2p[4];
    #pragma unroll
    for (int c = 0; c < 4; c++) {
        b1p[c] = pack2(bias1[tx * 8 + 2 * c], bias1[tx * 8 + 2 * c + 1]);
        b2p[c] = pack2(bias2[tx * 8 + 2 * c], bias2[tx * 8 + 2 * c + 1]);
    }

    for (int n0 = blockIdx.x * 128; n0 < NN; n0 += gridDim.x * 128) {
        __syncthreads();

        for (int i = tid; i < 128 * 16; i += 128) {
            int r = i >> 4, q = i & 15;
            int node = n0 + r;
            float4 v = make_float4(0.f, 0.f, 0.f, 0.f);
            if (node < NN)
                v = *(const float4*)(g_agg1 + (size_t)node * 64 + q * 4);
            float* p = buf + r * PAD + q * 4;
            p[0] = v.x; p[1] = v.y; p[2] = v.z; p[3] = v.w;
        }
        __syncthreads();

        // ---- layer 1 ----
        u64 acc[8][4];
        #pragma unroll
        for (int j = 0; j < 8; j++)
            #pragma unroll
            for (int c = 0; c < 4; c++) acc[j][c] = b1p[c];

        #pragma unroll 8
        for (int k = 0; k < 64; k++) {
            const u64* wr = (const u64*)(Wa + k * 64 + tx * 8);
            u64 w0 = wr[0], w1 = wr[1], w2 = wr[2], w3 = wr[3];
            #pragma unroll
            for (int j = 0; j < 8; j++) {
                float rv = buf[(ty * 8 + j) * PAD + k];
                u64 rp = pack2(rv, rv);
                ffma2(acc[j][0], rp, w0);
                ffma2(acc[j][1], rp, w1);
                ffma2(acc[j][2], rp, w2);
                ffma2(acc[j][3], rp, w3);
            }
        }
        __syncthreads();

        #pragma unroll
        for (int j = 0; j < 8; j++) {
            float* p = buf + (ty * 8 + j) * PAD + tx * 8;
            #pragma unroll
            for (int c = 0; c < 4; c++) {
                float lo, hi;
                unpack2(acc[j][c], lo, hi);
                p[2 * c]     = fmaxf(lo, 0.f);
                p[2 * c + 1] = fmaxf(hi, 0.f);
            }
        }
        __syncthreads();

        // ---- layer 2 ----
        u64 a2[8][4];
        #pragma unroll
        for (int j = 0; j < 8; j++)
            #pragma unroll
            for (int c = 0; c < 4; c++) a2[j][c] = b2p[c];

        #pragma unroll 8
        for (int k = 0; k < 64; k++) {
            const u64* wr = (const u64*)(Wb + k * 64 + tx * 8);
            u64 w0 = wr[0], w1 = wr[1], w2 = wr[2], w3 = wr[3];
            #pragma unroll
            for (int j = 0; j < 8; j++) {
                float rv = buf[(ty * 8 + j) * PAD + k];
                u64 rp = pack2(rv, rv);
                ffma2(a2[j][0], rp, w0);
                ffma2(a2[j][1], rp, w1);
                ffma2(a2[j][2], rp, w2);
                ffma2(a2[j][3], rp, w3);
            }
        }

        // relu -> fp16 -> store 8 cols (16 B) per row
        #pragma unroll
        for (int j = 0; j < 8; j++) {
            int node = n0 + ty * 8 + j;
            if (node >= NN) break;
            unsigned uu[4];
            #pragma unroll
            for (int c = 0; c < 4; c++) {
                float lo, hi;
                unpack2(a2[j][c], lo, hi);
                __half2 h = __floats2half2_rn(fmaxf(lo, 0.f), fmaxf(hi, 0.f));
                uu[c] = *(unsigned*)&h;
            }
            uint4 pack;
            pack.x = uu[0]; pack.y = uu[1]; pack.z = uu[2]; pack.w = uu[3];
            *(uint4*)(g_h1bh + (size_t)node * 64 + tx * 8) = pack;
        }
    }
}

// ---------------------------------------------------------------------------
// K5: MLP2 + pooling: h2 = relu(BN(agg2 @ W2 + b2)); xstruct[batch[i]] += h2
// ---------------------------------------------------------------------------
__global__ __launch_bounds__(128) void mlp2_kernel(
    const float* __restrict__ W2, const float* __restrict__ b2,
    const float* __restrict__ g2, const float* __restrict__ be2,
    const float* __restrict__ m2, const float* __restrict__ v2,
    const int* __restrict__ batch)
{
    extern __shared__ float sm[];
    float* Ws  = sm;                 // 4096 floats
    float* buf = sm + 4096;          // 128*PAD floats
    __shared__ float bias[64], scl[64];

    const int tid = threadIdx.x;
    const int tx  = tid & 7;
    const int ty  = tid >> 3;

    if (tid < 64) {
        float s = g2[tid] * rsqrtf(v2[tid] + BN_EPS);
        scl[tid]  = s;
        bias[tid] = b2[tid] * s + be2[tid] - m2[tid] * s;
    }
    __syncthreads();
    for (int i = tid; i < 4096; i += 128)
        Ws[i] = W2[i] * scl[i & 63];
    __syncthreads();

    u64 bp[4];
    #pragma unroll
    for (int c = 0; c < 4; c++)
        bp[c] = pack2(bias[tx * 8 + 2 * c], bias[tx * 8 + 2 * c + 1]);

    for (int n0 = blockIdx.x * 128; n0 < NN; n0 += gridDim.x * 128) {
        __syncthreads();

        for (int i = tid; i < 128 * 16; i += 128) {
            int r = i >> 4, q = i & 15;
            int node = n0 + r;
            float4 v = make_float4(0.f, 0.f, 0.f, 0.f);
            if (node < NN)
                v = *(const float4*)(g_agg2 + (size_t)node * 64 + q * 4);
            float* p = buf + r * PAD + q * 4;
            p[0] = v.x; p[1] = v.y; p[2] = v.z; p[3] = v.w;
        }
        __syncthreads();

        u64 acc[8][4];
        #pragma unroll
        for (int j = 0; j < 8; j++)
            #pragma unroll
            for (int c = 0; c < 4; c++) acc[j][c] = bp[c];

        #pragma unroll 8
        for (int k = 0; k < 64; k++) {
            const u64* wr = (const u64*)(Ws + k * 64 + tx * 8);
            u64 w0 = wr[0], w1 = wr[1], w2 = wr[2], w3 = wr[3];
            #pragma unroll
            for (int j = 0; j < 8; j++) {
                float rv = buf[(ty * 8 + j) * PAD + k];
                u64 rp = pack2(rv, rv);
                ffma2(acc[j][0], rp, w0);
                ffma2(acc[j][1], rp, w1);
                ffma2(acc[j][2], rp, w2);
                ffma2(acc[j][3], rp, w3);
            }
        }

        #pragma unroll
        for (int j = 0; j < 8; j++) {
            int node = n0 + ty * 8 + j;
            if (node >= NN) break;
            float o[8];
            #pragma unroll
            for (int c = 0; c < 4; c++) {
                unpack2(acc[j][c], o[2 * c], o[2 * c + 1]);
                o[2 * c]     = fmaxf(o[2 * c], 0.f);
                o[2 * c + 1] = fmaxf(o[2 * c + 1], 0.f);
            }
            int g = batch[node];
            float* dst = g_xstruct + (size_t)g * 64 + tx * 8;
            red_add_v4(dst,     make_float4(o[0], o[1], o[2], o[3]));
            red_add_v4(dst + 4, make_float4(o[4], o[5], o[6], o[7]));
        }
    }
}

// ---------------------------------------------------------------------------
// K6: x_topo = relu(topo @ Wt + bt); out = [xstruct, x_topo] @ Wc + bc
// ---------------------------------------------------------------------------
__global__ __launch_bounds__(256) void final_kernel(
    const float* __restrict__ topo, const float* __restrict__ Wt,
    const float* __restrict__ bt,   const float* __restrict__ Wc,
    const float* __restrict__ bc,   float* __restrict__ out)
{
    __shared__ float Wts[64 * 64];
    __shared__ float Wcs[128 * CC];
    __shared__ float bts[64], bcs[CC];
    __shared__ float trow[4][64];
    __shared__ float xt[4][64];
    __shared__ float xs[4][64];

    const int tx = threadIdx.x;   // 0..63
    const int ty = threadIdx.y;   // 0..3
    const int tid = ty * 64 + tx;

    for (int i = tid; i < 4096; i += 256) Wts[i] = Wt[i];
    for (int i = tid; i < 128 * CC; i += 256) Wcs[i] = Wc[i];
    if (tid < 64) bts[tid] = bt[tid];
    if (tid < CC) bcs[tid] = bc[tid];
    __syncthreads();

    for (int g0 = blockIdx.x * 4; g0 < BB; g0 += gridDim.x * 4) {
        int g = g0 + ty;
        bool valid = g < BB;
        if (valid) {
            trow[ty][tx] = topo[g * 64 + tx];
            xs[ty][tx]   = g_xstruct[g * 64 + tx];
        }
        __syncthreads();
        if (valid) {
            float acc = bts[tx];
            #pragma unroll 16
            for (int k = 0; k < 64; k++)
                acc += trow[ty][k] * Wts[k * 64 + tx];
            xt[ty][tx] = fmaxf(acc, 0.f);
        }
        __syncthreads();
        if (valid && tx < CC) {
            float acc = bcs[tx];
            #pragma unroll 16
            for (int k = 0; k < 64; k++) {
                acc += xs[ty][k] * Wcs[k * CC + tx];
                acc += xt[ty][k] * Wcs[(64 + k) * CC + tx];
            }
            out[g * CC + tx] = acc;
        }
        __syncthreads();
    }
}

// ---------------------------------------------------------------------------
extern "C" void kernel_launch(void* const* d_in, const int* in_sizes, int n_in,
                              void* d_out, int out_size) {
    const float* x    = (const float*)d_in[0];
    const int*   ei   = (const int*)d_in[1];
    const int*   batch= (const int*)d_in[2];
    const float* topo = (const float*)d_in[3];
    const float* W1a  = (const float*)d_in[4];
    const float* b1a  = (const float*)d_in[5];
    const float* g1   = (const float*)d_in[6];
    const float* be1  = (const float*)d_in[7];
    const float* m1   = (const float*)d_in[8];
    const float* v1   = (const float*)d_in[9];
    const float* W1b  = (const float*)d_in[10];
    const float* b1b  = (const float*)d_in[11];
    const float* W2   = (const float*)d_in[12];
    const float* b2   = (const float*)d_in[13];
    const float* g2   = (const float*)d_in[14];
    const float* be2  = (const float*)d_in[15];
    const float* m2   = (const float*)d_in[16];
    const float* v2   = (const float*)d_in[17];
    const float* Wt   = (const float*)d_in[18];
    const float* bt   = (const float*)d_in[19];
    const float* Wc   = (const float*)d_in[20];
    const float* bc   = (const float*)d_in[21];
    float* out = (float*)d_out;

    const int smem1 = (4096 + 4096 + 128 * PAD) * (int)sizeof(float);  // ~66 KB
    const int smem2 = (4096 + 128 * PAD) * (int)sizeof(float);         // ~50 KB
    static bool attr_set = false;
    if (!attr_set) {
        cudaFuncSetAttribute(mlp1_kernel,
                             cudaFuncAttributeMaxDynamicSharedMemorySize, smem1);
        cudaFuncSetAttribute(mlp2_kernel,
                             cudaFuncAttributeMaxDynamicSharedMemorySize, smem2);
        attr_set = true;
    }

    const int NB = (NN + 255) / 256;         // 391
    dim3 finBlock(64, 4);

    // CSR build + fp16 conversion
    prep_kernel<<<(NN * HH / 4 + 255) / 256, 256>>>(x);
    hist_kernel<<<(EE + 255) / 256, 256>>>(ei);
    bsum_kernel<<<NB, 256>>>();
    rowptr_kernel<<<NB, 256>>>();
    scatter_kernel<<<(EE + 255) / 256, 256>>>(ei);

    // Layer 1
    agg1_kernel<<<(NN * 16 + 255) / 256, 256>>>(x);
    mlp1_kernel<<<444, 128, smem1>>>(W1a, b1a, g1, be1, m1, v1, W1b, b1b);

    // Layer 2
    agg2_kernel<<<(NN * 16 + 255) / 256, 256>>>();
    mlp2_kernel<<<444, 128, smem2>>>(W2, b2, g2, be2, m2, v2, batch);

    final_kernel<<<64, finBlock>>>(topo, Wt, bt, Wc, bc, out);
}